// round 7
// baseline (speedup 1.0000x reference)
#include <cuda_runtime.h>
#include <math.h>

namespace {
constexpr int Bb = 2;          // batch
constexpr int Sn = 2048;       // sequence
constexpr int Hh = 8;          // heads
constexpr int Dd = 64;         // head dim
constexpr int Dm = 512;        // Hh*Dd
constexpr int Rows = Bb * Sn;  // 4096
constexpr float EPSv = 1e-4f;
constexpr float SCALEv = 0.125f;  // 64^-0.5
}

// Scratch (8 MB each) — device globals, no runtime allocation.
__device__ float g_q[Rows * Dm];
__device__ float g_k[Rows * Dm];
__device__ float g_v[Rows * Dm];
__device__ float g_o[Rows * Dm];

// ---------------------------------------------------------------------------
// C[M,Nc] = A[M,K] @ B[Nc,K]^T   (all row-major). 64x64 tile, BK=16, 256 thr.
// ---------------------------------------------------------------------------
__global__ __launch_bounds__(256) void sgemm_nt(
    const float* __restrict__ A, const float* __restrict__ Bw,
    float* __restrict__ C, int M, int Nc, int K)
{
    __shared__ float As[64][16];   // [m][k] — broadcast scalar reads
    __shared__ float Bs[16][68];   // [k][n] — float4 reads, pad for alignment

    const int tid = threadIdx.x;
    const int tx = tid & 15, ty = tid >> 4;
    const int m0 = blockIdx.y * 64, n0 = blockIdx.x * 64;
    const int lr = tid >> 2, lc4 = tid & 3;   // load mapping: 64 rows x 4 float4

    float acc[4][4] = {};

    for (int k0 = 0; k0 < K; k0 += 16) {
        float4 av = *(const float4*)&A[(size_t)(m0 + lr) * K + k0 + lc4 * 4];
        *(float4*)&As[lr][lc4 * 4] = av;
        float4 bv = *(const float4*)&Bw[(size_t)(n0 + lr) * K + k0 + lc4 * 4];
        Bs[lc4 * 4 + 0][lr] = bv.x;
        Bs[lc4 * 4 + 1][lr] = bv.y;
        Bs[lc4 * 4 + 2][lr] = bv.z;
        Bs[lc4 * 4 + 3][lr] = bv.w;
        __syncthreads();

        #pragma unroll
        for (int kk = 0; kk < 16; ++kk) {
            float4 b = *(float4*)&Bs[kk][tx * 4];
            float a0 = As[ty * 4 + 0][kk];
            float a1 = As[ty * 4 + 1][kk];
            float a2 = As[ty * 4 + 2][kk];
            float a3 = As[ty * 4 + 3][kk];
            acc[0][0] += a0 * b.x; acc[0][1] += a0 * b.y; acc[0][2] += a0 * b.z; acc[0][3] += a0 * b.w;
            acc[1][0] += a1 * b.x; acc[1][1] += a1 * b.y; acc[1][2] += a1 * b.z; acc[1][3] += a1 * b.w;
            acc[2][0] += a2 * b.x; acc[2][1] += a2 * b.y; acc[2][2] += a2 * b.z; acc[2][3] += a2 * b.w;
            acc[3][0] += a3 * b.x; acc[3][1] += a3 * b.y; acc[3][2] += a3 * b.z; acc[3][3] += a3 * b.w;
        }
        __syncthreads();
    }

    #pragma unroll
    for (int i = 0; i < 4; ++i) {
        float4 o = make_float4(acc[i][0], acc[i][1], acc[i][2], acc[i][3]);
        *(float4*)&C[(size_t)(m0 + ty * 4 + i) * Nc + n0 + tx * 4] = o;
    }
}

// ---------------------------------------------------------------------------
// RMS-magnitude normalize each contiguous 64-float head vector:
//   t *= mul / (sqrt(mean(t^2)) + eps).  One warp per chunk.
// ---------------------------------------------------------------------------
__global__ __launch_bounds__(256) void rmsnorm_kernel(
    float* __restrict__ t, float mul, int nchunks)
{
    int gw = (int)((blockIdx.x * blockDim.x + threadIdx.x) >> 5);
    int lane = threadIdx.x & 31;
    if (gw >= nchunks) return;
    float2* p = (float2*)(t + (size_t)gw * 64);
    float2 v = p[lane];
    float ss = v.x * v.x + v.y * v.y;
    #pragma unroll
    for (int m = 16; m > 0; m >>= 1) ss += __shfl_xor_sync(0xffffffffu, ss, m);
    float inv = mul / (sqrtf(ss * (1.0f / 64.0f)) + EPSv);
    v.x *= inv; v.y *= inv;
    p[lane] = v;
}

// ---------------------------------------------------------------------------
// Flash-style attention. Block = 64 queries of one (b,h). BN=64 KV tiles.
// 256 threads, 4x4 S/O micro-tile per thread. Scale already folded into Q.
// Dynamic smem: Qs[64][68] + Kst[64][68] + Vs[64][68] + Ps[64][68] = 69632 B.
// ---------------------------------------------------------------------------
__global__ __launch_bounds__(256) void attn_kernel()
{
    extern __shared__ float sm[];
    float* Qs  = sm;                // [r][d] row-major
    float* Kst = sm + 64 * 68;      // [d][c] transposed
    float* Vs  = sm + 2 * 64 * 68;  // [j][c]
    float* Ps  = sm + 3 * 64 * 68;  // [r][j]

    const int tid = threadIdx.x;
    const int tx = tid & 15, ty = tid >> 4;
    const int qt = blockIdx.x, h = blockIdx.y, b = blockIdx.z;
    const int qrow0 = b * Sn + qt * 64;
    const int hoff = h * Dd;

    // Load Q tile (64 x 64 floats = 1024 float4, 4 per thread)
    #pragma unroll
    for (int it = 0; it < 4; ++it) {
        int idx = tid + it * 256;
        int r = idx >> 4, c4 = idx & 15;
        float4 v = *(const float4*)&g_q[(size_t)(qrow0 + r) * Dm + hoff + c4 * 4];
        *(float4*)&Qs[r * 68 + c4 * 4] = v;
    }

    float m_i[4], l_i[4], acc[4][4];
    #pragma unroll
    for (int i = 0; i < 4; ++i) {
        m_i[i] = -1e30f; l_i[i] = 0.0f;
        #pragma unroll
        for (int j = 0; j < 4; ++j) acc[i][j] = 0.0f;
    }

    for (int kt = 0; kt < Sn / 64; ++kt) {
        __syncthreads();  // previous iteration done with Kst/Vs/Ps (also covers Q load)
        const int krow0 = b * Sn + kt * 64;
        #pragma unroll
        for (int it = 0; it < 4; ++it) {
            int idx = tid + it * 256;
            int r = idx >> 4, c4 = idx & 15;
            float4 kv = *(const float4*)&g_k[(size_t)(krow0 + r) * Dm + hoff + c4 * 4];
            Kst[(c4 * 4 + 0) * 68 + r] = kv.x;
            Kst[(c4 * 4 + 1) * 68 + r] = kv.y;
            Kst[(c4 * 4 + 2) * 68 + r] = kv.z;
            Kst[(c4 * 4 + 3) * 68 + r] = kv.w;
            float4 vv = *(const float4*)&g_v[(size_t)(krow0 + r) * Dm + hoff + c4 * 4];
            *(float4*)&Vs[r * 68 + c4 * 4] = vv;
        }
        __syncthreads();

        // S = Q K^T  (scale folded into Q)
        float s[4][4] = {};
        #pragma unroll 8
        for (int d = 0; d < 64; ++d) {
            float4 kv = *(float4*)&Kst[d * 68 + tx * 4];
            #pragma unroll
            for (int i = 0; i < 4; ++i) {
                float a = Qs[(ty * 4 + i) * 68 + d];
                s[i][0] += a * kv.x; s[i][1] += a * kv.y;
                s[i][2] += a * kv.z; s[i][3] += a * kv.w;
            }
        }

        // Online softmax (row reductions over 16 lanes of the half-warp)
        #pragma unroll
        for (int i = 0; i < 4; ++i) {
            float mx = fmaxf(fmaxf(s[i][0], s[i][1]), fmaxf(s[i][2], s[i][3]));
            #pragma unroll
            for (int m = 8; m > 0; m >>= 1)
                mx = fmaxf(mx, __shfl_xor_sync(0xffffffffu, mx, m));
            float mnew = fmaxf(m_i[i], mx);
            float alpha = __expf(m_i[i] - mnew);
            float rs = 0.0f;
            #pragma unroll
            for (int j = 0; j < 4; ++j) {
                float p = __expf(s[i][j] - mnew);
                s[i][j] = p;
                rs += p;
            }
            #pragma unroll
            for (int m = 8; m > 0; m >>= 1)
                rs += __shfl_xor_sync(0xffffffffu, rs, m);
            l_i[i] = l_i[i] * alpha + rs;
            m_i[i] = mnew;
            #pragma unroll
            for (int j = 0; j < 4; ++j) acc[i][j] *= alpha;
            #pragma unroll
            for (int j = 0; j < 4; ++j)
                Ps[(ty * 4 + i) * 68 + tx * 4 + j] = s[i][j];
        }
        __syncthreads();

        // acc += P @ V
        #pragma unroll 8
        for (int j = 0; j < 64; ++j) {
            float4 vv = *(float4*)&Vs[j * 68 + tx * 4];
            #pragma unroll
            for (int i = 0; i < 4; ++i) {
                float p = Ps[(ty * 4 + i) * 68 + j];
                acc[i][0] += p * vv.x; acc[i][1] += p * vv.y;
                acc[i][2] += p * vv.z; acc[i][3] += p * vv.w;
            }
        }
    }

    #pragma unroll
    for (int i = 0; i < 4; ++i) {
        float inv = 1.0f / l_i[i];
        float4 o = make_float4(acc[i][0] * inv, acc[i][1] * inv,
                               acc[i][2] * inv, acc[i][3] * inv);
        *(float4*)&g_o[(size_t)(qrow0 + ty * 4 + i) * Dm + hoff + tx * 4] = o;
    }
}

// ---------------------------------------------------------------------------
extern "C" void kernel_launch(void* const* d_in, const int* in_sizes, int n_in,
                              void* d_out, int out_size)
{
    (void)in_sizes; (void)n_in; (void)out_size;
    const float* x    = (const float*)d_in[0];
    const float* Wq   = (const float*)d_in[1];
    const float* Wkv  = (const float*)d_in[2];
    const float* Wout = (const float*)d_in[3];
    float* out = (float*)d_out;

    float *q, *k, *v, *o;
    cudaGetSymbolAddress((void**)&q, g_q);
    cudaGetSymbolAddress((void**)&k, g_k);
    cudaGetSymbolAddress((void**)&v, g_v);
    cudaGetSymbolAddress((void**)&o, g_o);

    cudaFuncSetAttribute(attn_kernel,
                         cudaFuncAttributeMaxDynamicSharedMemorySize, 69632);

    dim3 blk(256);
    dim3 ggrid(Dm / 64, Rows / 64);

    // Projections
    sgemm_nt<<<ggrid, blk>>>(x, Wq, q, Rows, Dm, Dm);
    sgemm_nt<<<ggrid, blk>>>(x, Wkv, k, Rows, Dm, Dm);
    sgemm_nt<<<ggrid, blk>>>(x, Wkv + (size_t)Dm * Dm, v, Rows, Dm, Dm);

    // Cosine normalization (attention scale folded into q)
    int nchunks = Rows * Hh;  // 32768
    rmsnorm_kernel<<<nchunks / 8, 256>>>(q, SCALEv, nchunks);
    rmsnorm_kernel<<<nchunks / 8, 256>>>(k, 1.0f, nchunks);

    // Attention
    attn_kernel<<<dim3(Sn / 64, Hh, Bb), blk, 69632>>>();

    // Output projection
    sgemm_nt<<<ggrid, blk>>>(o, Wout, out, Rows, Dm, Dm);
}

// round 8
// speedup vs baseline: 3.3805x; 3.3805x over previous
#include <cuda_runtime.h>
#include <math.h>
#include <stdint.h>

namespace {
constexpr int Bb = 2;          // batch
constexpr int Sn = 2048;       // sequence
constexpr int Hh = 8;          // heads
constexpr int Dd = 64;         // head dim
constexpr int Dm = 512;        // Hh*Dd
constexpr int Rows = Bb * Sn;  // 4096
constexpr float EPSv = 1e-4f;
constexpr float SCALEv = 0.125f;       // 64^-0.5
constexpr float LOG2E = 1.4426950408889634f;
}

// Scratch (8 MB each) — device globals, no runtime allocation.
__device__ float g_q[Rows * Dm];
__device__ float g_k[Rows * Dm];
__device__ float g_v[Rows * Dm];
__device__ float g_o[Rows * Dm];

// ---------------------------------------------------------------------------
// helpers
// ---------------------------------------------------------------------------
__device__ __forceinline__ uint32_t f2tf(float f) {
    uint32_t u;
    asm("cvt.rna.tf32.f32 %0, %1;" : "=r"(u) : "f"(f));
    return u;
}
__device__ __forceinline__ float exp2a(float x) {
    float y;
    asm("ex2.approx.ftz.f32 %0, %1;" : "=f"(y) : "f"(x));
    return y;
}
__device__ __forceinline__ void mma_tf32(float c[4], const uint32_t a[4],
                                         uint32_t b0, uint32_t b1) {
    asm volatile(
        "mma.sync.aligned.m16n8k8.row.col.f32.tf32.tf32.f32 "
        "{%0,%1,%2,%3}, {%4,%5,%6,%7}, {%8,%9}, {%0,%1,%2,%3};\n"
        : "+f"(c[0]), "+f"(c[1]), "+f"(c[2]), "+f"(c[3])
        : "r"(a[0]), "r"(a[1]), "r"(a[2]), "r"(a[3]), "r"(b0), "r"(b1));
}

// ---------------------------------------------------------------------------
// C[M,Nc] = A[M,K] @ B[Nc,K]^T (row-major), tf32 tensor-core GEMM.
// 128x128 tile, BK=16, 256 threads (8 warps as 4m x 2n, warp tile 32x64).
// Smem stride 20 -> conflict-free fragment loads for both A- and B-patterns.
// ---------------------------------------------------------------------------
__global__ __launch_bounds__(256) void gemm_tf32(
    const float* __restrict__ A, const float* __restrict__ Bw,
    float* __restrict__ C, int M, int Nc, int K)
{
    __shared__ uint32_t As[128 * 20];
    __shared__ uint32_t Bs[128 * 20];

    const int tid  = threadIdx.x;
    const int lane = tid & 31, wid = tid >> 5;
    const int grp  = lane >> 2, tg = lane & 3;
    const int wm   = wid >> 1,  wn = wid & 1;
    const int m0   = blockIdx.y * 128, n0 = blockIdx.x * 128;

    float c[2][8][4];
    #pragma unroll
    for (int mt = 0; mt < 2; ++mt)
        #pragma unroll
        for (int nt = 0; nt < 8; ++nt)
            #pragma unroll
            for (int i = 0; i < 4; ++i) c[mt][nt][i] = 0.0f;

    // prefetch first tile
    float4 ra[2], rb[2];
    #pragma unroll
    for (int it = 0; it < 2; ++it) {
        int lin = tid + it * 256;
        int r = lin >> 2, c4 = (lin & 3) * 4;
        ra[it] = *(const float4*)&A [(size_t)(m0 + r) * K + c4];
        rb[it] = *(const float4*)&Bw[(size_t)(n0 + r) * K + c4];
    }

    for (int k0 = 0; k0 < K; k0 += 16) {
        // stage current tile into smem (convert to tf32 bits)
        #pragma unroll
        for (int it = 0; it < 2; ++it) {
            int lin = tid + it * 256;
            int r = lin >> 2, c4 = (lin & 3) * 4;
            uint32_t* pa = &As[r * 20 + c4];
            pa[0] = f2tf(ra[it].x); pa[1] = f2tf(ra[it].y);
            pa[2] = f2tf(ra[it].z); pa[3] = f2tf(ra[it].w);
            uint32_t* pb = &Bs[r * 20 + c4];
            pb[0] = f2tf(rb[it].x); pb[1] = f2tf(rb[it].y);
            pb[2] = f2tf(rb[it].z); pb[3] = f2tf(rb[it].w);
        }
        __syncthreads();

        // prefetch next tile during mma
        if (k0 + 16 < K) {
            #pragma unroll
            for (int it = 0; it < 2; ++it) {
                int lin = tid + it * 256;
                int r = lin >> 2, c4 = (lin & 3) * 4;
                ra[it] = *(const float4*)&A [(size_t)(m0 + r) * K + k0 + 16 + c4];
                rb[it] = *(const float4*)&Bw[(size_t)(n0 + r) * K + k0 + 16 + c4];
            }
        }

        #pragma unroll
        for (int ks = 0; ks < 2; ++ks) {
            uint32_t a[2][4];
            #pragma unroll
            for (int mt = 0; mt < 2; ++mt) {
                const uint32_t* p = &As[(wm * 32 + mt * 16 + grp) * 20 + ks * 8 + tg];
                a[mt][0] = p[0];       a[mt][2] = p[4];
                a[mt][1] = p[20 * 8];  a[mt][3] = p[20 * 8 + 4];
            }
            #pragma unroll
            for (int nt = 0; nt < 8; ++nt) {
                const uint32_t* p = &Bs[(wn * 64 + nt * 8 + grp) * 20 + ks * 8 + tg];
                uint32_t b0 = p[0], b1 = p[4];
                mma_tf32(c[0][nt], a[0], b0, b1);
                mma_tf32(c[1][nt], a[1], b0, b1);
            }
        }
        __syncthreads();
    }

    #pragma unroll
    for (int mt = 0; mt < 2; ++mt) {
        int row = m0 + wm * 32 + mt * 16 + grp;
        #pragma unroll
        for (int nt = 0; nt < 8; ++nt) {
            int col = n0 + wn * 64 + nt * 8 + tg * 2;
            *(float2*)&C[(size_t)row * Nc + col] =
                make_float2(c[mt][nt][0], c[mt][nt][1]);
            *(float2*)&C[(size_t)(row + 8) * Nc + col] =
                make_float2(c[mt][nt][2], c[mt][nt][3]);
        }
    }
}

// ---------------------------------------------------------------------------
// RMS-magnitude normalize each contiguous 64-float head vector.
// ---------------------------------------------------------------------------
__global__ __launch_bounds__(256) void rmsnorm_kernel(
    float* __restrict__ t, float mul, int nchunks)
{
    int gw = (int)((blockIdx.x * blockDim.x + threadIdx.x) >> 5);
    int lane = threadIdx.x & 31;
    if (gw >= nchunks) return;
    float2* p = (float2*)(t + (size_t)gw * 64);
    float2 v = p[lane];
    float ss = v.x * v.x + v.y * v.y;
    #pragma unroll
    for (int m = 16; m > 0; m >>= 1) ss += __shfl_xor_sync(0xffffffffu, ss, m);
    float inv = mul / (sqrtf(ss * (1.0f / 64.0f)) + EPSv);
    v.x *= inv; v.y *= inv;
    p[lane] = v;
}

// ---------------------------------------------------------------------------
// Flash attention, tf32 tensor cores. CTA = 128 queries of one (b,h),
// 4 warps (each 32 rows x full 64-key width). KV streamed in 64-key tiles.
// Q (log2-domain scale folded) and K/V converted to tf32 in smem.
// Smem strides: Q/K/P 68 (A/B-pattern conflict-free), V 72 (row=tg pattern).
// Dynamic smem = (128+64+128)*68*4 + 64*72*4 = 105472 B.
// ---------------------------------------------------------------------------
__global__ __launch_bounds__(128) void attn_tf32()
{
    extern __shared__ uint32_t sm[];
    uint32_t* Qs = sm;                 // [128][68]
    uint32_t* Ks = Qs + 128 * 68;      // [64][68]
    uint32_t* Ps = Ks + 64 * 68;       // [128][68]
    uint32_t* Vs = Ps + 128 * 68;      // [64][72]

    const int tid  = threadIdx.x;
    const int lane = tid & 31, wid = tid >> 5;
    const int grp  = lane >> 2, tg = lane & 3;
    const int row0 = wid * 32;
    const int qt = blockIdx.x, h = blockIdx.y, b = blockIdx.z;
    const int qrow0 = b * Sn + qt * 128;
    const int hoff  = h * Dd;

    // Load Q tile: 128x64 floats = 2048 float4, 16 per thread.
    #pragma unroll
    for (int it = 0; it < 16; ++it) {
        int lin = tid + it * 128;
        int r = lin >> 4, c4 = (lin & 15) * 4;
        float4 v = *(const float4*)&g_q[(size_t)(qrow0 + r) * Dm + hoff + c4];
        uint32_t* p = &Qs[r * 68 + c4];
        p[0] = f2tf(v.x); p[1] = f2tf(v.y); p[2] = f2tf(v.z); p[3] = f2tf(v.w);
    }

    float o[2][8][4];
    float mrow[2][2], lrow[2][2];
    #pragma unroll
    for (int mt = 0; mt < 2; ++mt) {
        mrow[mt][0] = mrow[mt][1] = -1e30f;
        lrow[mt][0] = lrow[mt][1] = 0.0f;
        #pragma unroll
        for (int nt = 0; nt < 8; ++nt)
            #pragma unroll
            for (int i = 0; i < 4; ++i) o[mt][nt][i] = 0.0f;
    }

    for (int kt = 0; kt < Sn / 64; ++kt) {
        __syncthreads();   // K/V reuse fence (also covers initial Q staging)
        const int krow0 = b * Sn + kt * 64;
        #pragma unroll
        for (int it = 0; it < 8; ++it) {
            int lin = tid + it * 128;
            int r = lin >> 4, c4 = (lin & 15) * 4;
            float4 kv = *(const float4*)&g_k[(size_t)(krow0 + r) * Dm + hoff + c4];
            uint32_t* pk = &Ks[r * 68 + c4];
            pk[0] = f2tf(kv.x); pk[1] = f2tf(kv.y);
            pk[2] = f2tf(kv.z); pk[3] = f2tf(kv.w);
            float4 vv = *(const float4*)&g_v[(size_t)(krow0 + r) * Dm + hoff + c4];
            uint32_t* pv = &Vs[r * 72 + c4];
            pv[0] = f2tf(vv.x); pv[1] = f2tf(vv.y);
            pv[2] = f2tf(vv.z); pv[3] = f2tf(vv.w);
        }
        __syncthreads();

        // ---- S = Q K^T (scale*log2e folded into Q) ----
        float s[2][8][4];
        #pragma unroll
        for (int mt = 0; mt < 2; ++mt)
            #pragma unroll
            for (int nt = 0; nt < 8; ++nt)
                #pragma unroll
                for (int i = 0; i < 4; ++i) s[mt][nt][i] = 0.0f;

        #pragma unroll
        for (int ks = 0; ks < 8; ++ks) {
            uint32_t a[2][4];
            #pragma unroll
            for (int mt = 0; mt < 2; ++mt) {
                const uint32_t* p = &Qs[(row0 + mt * 16 + grp) * 68 + ks * 8 + tg];
                a[mt][0] = p[0];       a[mt][2] = p[4];
                a[mt][1] = p[68 * 8];  a[mt][3] = p[68 * 8 + 4];
            }
            #pragma unroll
            for (int nt = 0; nt < 8; ++nt) {
                const uint32_t* p = &Ks[(nt * 8 + grp) * 68 + ks * 8 + tg];
                uint32_t b0 = p[0], b1 = p[4];
                mma_tf32(s[0][nt], a[0], b0, b1);
                mma_tf32(s[1][nt], a[1], b0, b1);
            }
        }

        // ---- online softmax (rows live in quads: shfl xor 1,2) ----
        #pragma unroll
        for (int mt = 0; mt < 2; ++mt) {
            #pragma unroll
            for (int rh = 0; rh < 2; ++rh) {
                float mx = -1e30f;
                #pragma unroll
                for (int nt = 0; nt < 8; ++nt)
                    mx = fmaxf(mx, fmaxf(s[mt][nt][rh * 2], s[mt][nt][rh * 2 + 1]));
                mx = fmaxf(mx, __shfl_xor_sync(0xffffffffu, mx, 1));
                mx = fmaxf(mx, __shfl_xor_sync(0xffffffffu, mx, 2));
                float mnew  = fmaxf(mrow[mt][rh], mx);
                float alpha = exp2a(mrow[mt][rh] - mnew);
                float rs = 0.0f;
                #pragma unroll
                for (int nt = 0; nt < 8; ++nt) {
                    float p0 = exp2a(s[mt][nt][rh * 2]     - mnew);
                    float p1 = exp2a(s[mt][nt][rh * 2 + 1] - mnew);
                    s[mt][nt][rh * 2] = p0; s[mt][nt][rh * 2 + 1] = p1;
                    rs += p0 + p1;
                }
                rs += __shfl_xor_sync(0xffffffffu, rs, 1);
                rs += __shfl_xor_sync(0xffffffffu, rs, 2);
                lrow[mt][rh] = lrow[mt][rh] * alpha + rs;
                mrow[mt][rh] = mnew;
                #pragma unroll
                for (int nt = 0; nt < 8; ++nt) {
                    o[mt][nt][rh * 2]     *= alpha;
                    o[mt][nt][rh * 2 + 1] *= alpha;
                }
            }
            // stash P (tf32) — this warp's rows only, read back only by itself
            #pragma unroll
            for (int nt = 0; nt < 8; ++nt) {
                uint32_t* p = &Ps[(row0 + mt * 16 + grp) * 68 + nt * 8 + tg * 2];
                p[0]          = f2tf(s[mt][nt][0]);
                p[1]          = f2tf(s[mt][nt][1]);
                p[68 * 8]     = f2tf(s[mt][nt][2]);
                p[68 * 8 + 1] = f2tf(s[mt][nt][3]);
            }
        }
        __syncwarp();

        // ---- O += P V ----
        #pragma unroll
        for (int ks = 0; ks < 8; ++ks) {
            uint32_t a[2][4];
            #pragma unroll
            for (int mt = 0; mt < 2; ++mt) {
                const uint32_t* p = &Ps[(row0 + mt * 16 + grp) * 68 + ks * 8 + tg];
                a[mt][0] = p[0];       a[mt][2] = p[4];
                a[mt][1] = p[68 * 8];  a[mt][3] = p[68 * 8 + 4];
            }
            #pragma unroll
            for (int nt = 0; nt < 8; ++nt) {
                uint32_t b0 = Vs[(ks * 8 + tg) * 72 + nt * 8 + grp];
                uint32_t b1 = Vs[(ks * 8 + tg + 4) * 72 + nt * 8 + grp];
                mma_tf32(o[0][nt], a[0], b0, b1);
                mma_tf32(o[1][nt], a[1], b0, b1);
            }
        }
    }

    // epilogue: normalize and store
    #pragma unroll
    for (int mt = 0; mt < 2; ++mt) {
        float inv0 = 1.0f / lrow[mt][0];
        float inv1 = 1.0f / lrow[mt][1];
        int row = qrow0 + row0 + mt * 16 + grp;
        #pragma unroll
        for (int nt = 0; nt < 8; ++nt) {
            int col = hoff + nt * 8 + tg * 2;
            *(float2*)&g_o[(size_t)row * Dm + col] =
                make_float2(o[mt][nt][0] * inv0, o[mt][nt][1] * inv0);
            *(float2*)&g_o[(size_t)(row + 8) * Dm + col] =
                make_float2(o[mt][nt][2] * inv1, o[mt][nt][3] * inv1);
        }
    }
}

// ---------------------------------------------------------------------------
extern "C" void kernel_launch(void* const* d_in, const int* in_sizes, int n_in,
                              void* d_out, int out_size)
{
    (void)in_sizes; (void)n_in; (void)out_size;
    const float* x    = (const float*)d_in[0];
    const float* Wq   = (const float*)d_in[1];
    const float* Wkv  = (const float*)d_in[2];
    const float* Wout = (const float*)d_in[3];
    float* out = (float*)d_out;

    float *q, *k, *v, *o;
    cudaGetSymbolAddress((void**)&q, g_q);
    cudaGetSymbolAddress((void**)&k, g_k);
    cudaGetSymbolAddress((void**)&v, g_v);
    cudaGetSymbolAddress((void**)&o, g_o);

    cudaFuncSetAttribute(attn_tf32,
                         cudaFuncAttributeMaxDynamicSharedMemorySize, 105472);

    dim3 blk(256);
    dim3 ggrid(Dm / 128, Rows / 128);   // (4, 32)

    // Projections (tf32 tensor cores)
    gemm_tf32<<<ggrid, blk>>>(x, Wq, q, Rows, Dm, Dm);
    gemm_tf32<<<ggrid, blk>>>(x, Wkv, k, Rows, Dm, Dm);
    gemm_tf32<<<ggrid, blk>>>(x, Wkv + (size_t)Dm * Dm, v, Rows, Dm, Dm);

    // Cosine normalization; fold attention scale AND log2e into q so the
    // softmax runs directly in exp2 domain.
    int nchunks = Rows * Hh;  // 32768
    rmsnorm_kernel<<<nchunks / 8, 256>>>(q, SCALEv * LOG2E, nchunks);
    rmsnorm_kernel<<<nchunks / 8, 256>>>(k, 1.0f, nchunks);

    // Attention
    attn_tf32<<<dim3(Sn / 128, Hh, Bb), 128, 105472>>>();

    // Output projection
    gemm_tf32<<<ggrid, blk>>>(o, Wout, out, Rows, Dm, Dm);
}

// round 9
// speedup vs baseline: 3.4060x; 1.0075x over previous
#include <cuda_runtime.h>
#include <math.h>
#include <stdint.h>

namespace {
constexpr int Bb = 2;          // batch
constexpr int Sn = 2048;       // sequence
constexpr int Hh = 8;          // heads
constexpr int Dd = 64;         // head dim
constexpr int Dm = 512;        // Hh*Dd
constexpr int Rows = Bb * Sn;  // 4096
constexpr float EPSv = 1e-4f;
constexpr float SCALEv = 0.125f;       // 64^-0.5
constexpr float LOG2E = 1.4426950408889634f;
}

// Scratch (8 MB each) — device globals, no runtime allocation.
__device__ float g_q[Rows * Dm];
__device__ float g_k[Rows * Dm];
__device__ float g_v[Rows * Dm];
__device__ float g_o[Rows * Dm];

// ---------------------------------------------------------------------------
// helpers
// ---------------------------------------------------------------------------
__device__ __forceinline__ uint32_t f2tf(float f) {
    uint32_t u;
    asm("cvt.rna.tf32.f32 %0, %1;" : "=r"(u) : "f"(f));
    return u;
}
__device__ __forceinline__ float exp2a(float x) {
    float y;
    asm("ex2.approx.ftz.f32 %0, %1;" : "=f"(y) : "f"(x));
    return y;
}
__device__ __forceinline__ void mma_tf32(float c[4], const uint32_t a[4],
                                         uint32_t b0, uint32_t b1) {
    asm volatile(
        "mma.sync.aligned.m16n8k8.row.col.f32.tf32.tf32.f32 "
        "{%0,%1,%2,%3}, {%4,%5,%6,%7}, {%8,%9}, {%0,%1,%2,%3};\n"
        : "+f"(c[0]), "+f"(c[1]), "+f"(c[2]), "+f"(c[3])
        : "r"(a[0]), "r"(a[1]), "r"(a[2]), "r"(a[3]), "r"(b0), "r"(b1));
}

// ---------------------------------------------------------------------------
// C[M,Nc] = A[M,K] @ B[Nc,K]^T (row-major), tf32 tensor-core GEMM.
// 128x128 tile, BK=16, 256 threads (8 warps as 4m x 2n, warp tile 32x64).
// Double-buffered smem (one sync per K-step); gmem prefetch overlaps MMA.
// If norm_mul != 0: per-row RMS-normalize each 64-wide head segment in the
// epilogue (each warp's 64-col segment is head-aligned; rows live in quads).
// ---------------------------------------------------------------------------
__global__ __launch_bounds__(256) void gemm_tf32(
    const float* __restrict__ A, const float* __restrict__ Bw,
    float* __restrict__ C, int M, int Nc, int K, float norm_mul)
{
    __shared__ uint32_t As[2][128 * 20];
    __shared__ uint32_t Bs[2][128 * 20];

    const int tid  = threadIdx.x;
    const int lane = tid & 31, wid = tid >> 5;
    const int grp  = lane >> 2, tg = lane & 3;
    const int wm   = wid >> 1,  wn = wid & 1;
    const int m0   = blockIdx.y * 128, n0 = blockIdx.x * 128;
    const int lr   = tid >> 2, lc4 = (tid & 3) * 4;

    float c[2][8][4];
    #pragma unroll
    for (int mt = 0; mt < 2; ++mt)
        #pragma unroll
        for (int nt = 0; nt < 8; ++nt)
            #pragma unroll
            for (int i = 0; i < 4; ++i) c[mt][nt][i] = 0.0f;

    float4 ra[2], rb[2];
    #pragma unroll
    for (int it = 0; it < 2; ++it) {
        int r = lr + it * 64;
        ra[it] = *(const float4*)&A [(size_t)(m0 + r) * K + lc4];
        rb[it] = *(const float4*)&Bw[(size_t)(n0 + r) * K + lc4];
    }
    #pragma unroll
    for (int it = 0; it < 2; ++it) {
        int r = lr + it * 64;
        uint32_t* pa = &As[0][r * 20 + lc4];
        pa[0] = f2tf(ra[it].x); pa[1] = f2tf(ra[it].y);
        pa[2] = f2tf(ra[it].z); pa[3] = f2tf(ra[it].w);
        uint32_t* pb = &Bs[0][r * 20 + lc4];
        pb[0] = f2tf(rb[it].x); pb[1] = f2tf(rb[it].y);
        pb[2] = f2tf(rb[it].z); pb[3] = f2tf(rb[it].w);
    }
    __syncthreads();

    int p = 0;
    for (int k0 = 0; k0 < K; k0 += 16) {
        const bool has_next = (k0 + 16) < K;
        if (has_next) {
            #pragma unroll
            for (int it = 0; it < 2; ++it) {
                int r = lr + it * 64;
                ra[it] = *(const float4*)&A [(size_t)(m0 + r) * K + k0 + 16 + lc4];
                rb[it] = *(const float4*)&Bw[(size_t)(n0 + r) * K + k0 + 16 + lc4];
            }
        }

        #pragma unroll
        for (int ks = 0; ks < 2; ++ks) {
            uint32_t a[2][4];
            #pragma unroll
            for (int mt = 0; mt < 2; ++mt) {
                const uint32_t* q = &As[p][(wm * 32 + mt * 16 + grp) * 20 + ks * 8 + tg];
                a[mt][0] = q[0];       a[mt][2] = q[4];
                a[mt][1] = q[20 * 8];  a[mt][3] = q[20 * 8 + 4];
            }
            #pragma unroll
            for (int nt = 0; nt < 8; ++nt) {
                const uint32_t* q = &Bs[p][(wn * 64 + nt * 8 + grp) * 20 + ks * 8 + tg];
                uint32_t b0 = q[0], b1 = q[4];
                mma_tf32(c[0][nt], a[0], b0, b1);
                mma_tf32(c[1][nt], a[1], b0, b1);
            }
        }

        if (has_next) {
            #pragma unroll
            for (int it = 0; it < 2; ++it) {
                int r = lr + it * 64;
                uint32_t* pa = &As[p ^ 1][r * 20 + lc4];
                pa[0] = f2tf(ra[it].x); pa[1] = f2tf(ra[it].y);
                pa[2] = f2tf(ra[it].z); pa[3] = f2tf(ra[it].w);
                uint32_t* pb = &Bs[p ^ 1][r * 20 + lc4];
                pb[0] = f2tf(rb[it].x); pb[1] = f2tf(rb[it].y);
                pb[2] = f2tf(rb[it].z); pb[3] = f2tf(rb[it].w);
            }
        }
        __syncthreads();
        p ^= 1;
    }

    // Epilogue: optional fused RMS-magnitude norm over each row's 64-col
    // head segment (warp-quad holds the full segment), then store.
    #pragma unroll
    for (int mt = 0; mt < 2; ++mt) {
        float sc0 = 1.0f, sc1 = 1.0f;
        if (norm_mul != 0.0f) {
            float ss0 = 0.0f, ss1 = 0.0f;
            #pragma unroll
            for (int nt = 0; nt < 8; ++nt) {
                ss0 += c[mt][nt][0] * c[mt][nt][0] + c[mt][nt][1] * c[mt][nt][1];
                ss1 += c[mt][nt][2] * c[mt][nt][2] + c[mt][nt][3] * c[mt][nt][3];
            }
            ss0 += __shfl_xor_sync(0xffffffffu, ss0, 1);
            ss0 += __shfl_xor_sync(0xffffffffu, ss0, 2);
            ss1 += __shfl_xor_sync(0xffffffffu, ss1, 1);
            ss1 += __shfl_xor_sync(0xffffffffu, ss1, 2);
            sc0 = norm_mul / (sqrtf(ss0 * (1.0f / 64.0f)) + EPSv);
            sc1 = norm_mul / (sqrtf(ss1 * (1.0f / 64.0f)) + EPSv);
        }
        int row = m0 + wm * 32 + mt * 16 + grp;
        #pragma unroll
        for (int nt = 0; nt < 8; ++nt) {
            int col = n0 + wn * 64 + nt * 8 + tg * 2;
            *(float2*)&C[(size_t)row * Nc + col] =
                make_float2(c[mt][nt][0] * sc0, c[mt][nt][1] * sc0);
            *(float2*)&C[(size_t)(row + 8) * Nc + col] =
                make_float2(c[mt][nt][2] * sc1, c[mt][nt][3] * sc1);
        }
    }
}

// ---------------------------------------------------------------------------
// Flash attention, tf32 tensor cores. CTA = 128 queries of one (b,h),
// 4 warps (each 32 rows x full 64-key width). KV streamed in 64-key tiles.
// __launch_bounds__(128, 2): regs<=256 so 2 CTAs/SM co-reside (2x105KB smem
// fits the 228KB SM) -> 8 warps/SM hide softmax/LDS/tensor latency.
// Dynamic smem = (128+64+128)*68*4 + 64*72*4 = 105472 B.
// ---------------------------------------------------------------------------
__global__ __launch_bounds__(128, 2) void attn_tf32()
{
    extern __shared__ uint32_t sm[];
    uint32_t* Qs = sm;                 // [128][68]
    uint32_t* Ks = Qs + 128 * 68;      // [64][68]
    uint32_t* Ps = Ks + 64 * 68;       // [128][68]
    uint32_t* Vs = Ps + 128 * 68;      // [64][72]

    const int tid  = threadIdx.x;
    const int lane = tid & 31, wid = tid >> 5;
    const int grp  = lane >> 2, tg = lane & 3;
    const int row0 = wid * 32;
    const int qt = blockIdx.x, h = blockIdx.y, b = blockIdx.z;
    const int qrow0 = b * Sn + qt * 128;
    const int hoff  = h * Dd;

    // Load Q tile: 128x64 floats = 2048 float4, 16 per thread.
    #pragma unroll
    for (int it = 0; it < 16; ++it) {
        int lin = tid + it * 128;
        int r = lin >> 4, c4 = (lin & 15) * 4;
        float4 v = *(const float4*)&g_q[(size_t)(qrow0 + r) * Dm + hoff + c4];
        uint32_t* p = &Qs[r * 68 + c4];
        p[0] = f2tf(v.x); p[1] = f2tf(v.y); p[2] = f2tf(v.z); p[3] = f2tf(v.w);
    }

    float o[2][8][4];
    float mrow[2][2], lrow[2][2];
    #pragma unroll
    for (int mt = 0; mt < 2; ++mt) {
        mrow[mt][0] = mrow[mt][1] = -1e30f;
        lrow[mt][0] = lrow[mt][1] = 0.0f;
        #pragma unroll
        for (int nt = 0; nt < 8; ++nt)
            #pragma unroll
            for (int i = 0; i < 4; ++i) o[mt][nt][i] = 0.0f;
    }

    for (int kt = 0; kt < Sn / 64; ++kt) {
        __syncthreads();   // K/V reuse fence (also covers initial Q staging)
        const int krow0 = b * Sn + kt * 64;
        #pragma unroll
        for (int it = 0; it < 8; ++it) {
            int lin = tid + it * 128;
            int r = lin >> 4, c4 = (lin & 15) * 4;
            float4 kv = *(const float4*)&g_k[(size_t)(krow0 + r) * Dm + hoff + c4];
            uint32_t* pk = &Ks[r * 68 + c4];
            pk[0] = f2tf(kv.x); pk[1] = f2tf(kv.y);
            pk[2] = f2tf(kv.z); pk[3] = f2tf(kv.w);
            float4 vv = *(const float4*)&g_v[(size_t)(krow0 + r) * Dm + hoff + c4];
            uint32_t* pv = &Vs[r * 72 + c4];
            pv[0] = f2tf(vv.x); pv[1] = f2tf(vv.y);
            pv[2] = f2tf(vv.z); pv[3] = f2tf(vv.w);
        }
        __syncthreads();

        // ---- S = Q K^T (scale*log2e folded into Q) ----
        float s[2][8][4];
        #pragma unroll
        for (int mt = 0; mt < 2; ++mt)
            #pragma unroll
            for (int nt = 0; nt < 8; ++nt)
                #pragma unroll
                for (int i = 0; i < 4; ++i) s[mt][nt][i] = 0.0f;

        #pragma unroll
        for (int ks = 0; ks < 8; ++ks) {
            uint32_t a[2][4];
            #pragma unroll
            for (int mt = 0; mt < 2; ++mt) {
                const uint32_t* p = &Qs[(row0 + mt * 16 + grp) * 68 + ks * 8 + tg];
                a[mt][0] = p[0];       a[mt][2] = p[4];
                a[mt][1] = p[68 * 8];  a[mt][3] = p[68 * 8 + 4];
            }
            #pragma unroll
            for (int nt = 0; nt < 8; ++nt) {
                const uint32_t* p = &Ks[(nt * 8 + grp) * 68 + ks * 8 + tg];
                uint32_t b0 = p[0], b1 = p[4];
                mma_tf32(s[0][nt], a[0], b0, b1);
                mma_tf32(s[1][nt], a[1], b0, b1);
            }
        }

        // ---- online softmax (rows live in quads: shfl xor 1,2) ----
        #pragma unroll
        for (int mt = 0; mt < 2; ++mt) {
            #pragma unroll
            for (int rh = 0; rh < 2; ++rh) {
                float mx = -1e30f;
                #pragma unroll
                for (int nt = 0; nt < 8; ++nt)
                    mx = fmaxf(mx, fmaxf(s[mt][nt][rh * 2], s[mt][nt][rh * 2 + 1]));
                mx = fmaxf(mx, __shfl_xor_sync(0xffffffffu, mx, 1));
                mx = fmaxf(mx, __shfl_xor_sync(0xffffffffu, mx, 2));
                float mnew  = fmaxf(mrow[mt][rh], mx);
                float alpha = exp2a(mrow[mt][rh] - mnew);
                float rs = 0.0f;
                #pragma unroll
                for (int nt = 0; nt < 8; ++nt) {
                    float p0 = exp2a(s[mt][nt][rh * 2]     - mnew);
                    float p1 = exp2a(s[mt][nt][rh * 2 + 1] - mnew);
                    s[mt][nt][rh * 2] = p0; s[mt][nt][rh * 2 + 1] = p1;
                    rs += p0 + p1;
                }
                rs += __shfl_xor_sync(0xffffffffu, rs, 1);
                rs += __shfl_xor_sync(0xffffffffu, rs, 2);
                lrow[mt][rh] = lrow[mt][rh] * alpha + rs;
                mrow[mt][rh] = mnew;
                #pragma unroll
                for (int nt = 0; nt < 8; ++nt) {
                    o[mt][nt][rh * 2]     *= alpha;
                    o[mt][nt][rh * 2 + 1] *= alpha;
                }
            }
            // stash P (tf32) — this warp's rows only, read back only by itself
            #pragma unroll
            for (int nt = 0; nt < 8; ++nt) {
                uint32_t* p = &Ps[(row0 + mt * 16 + grp) * 68 + nt * 8 + tg * 2];
                p[0]          = f2tf(s[mt][nt][0]);
                p[1]          = f2tf(s[mt][nt][1]);
                p[68 * 8]     = f2tf(s[mt][nt][2]);
                p[68 * 8 + 1] = f2tf(s[mt][nt][3]);
            }
        }
        __syncwarp();

        // ---- O += P V ----
        #pragma unroll
        for (int ks = 0; ks < 8; ++ks) {
            uint32_t a[2][4];
            #pragma unroll
            for (int mt = 0; mt < 2; ++mt) {
                const uint32_t* p = &Ps[(row0 + mt * 16 + grp) * 68 + ks * 8 + tg];
                a[mt][0] = p[0];       a[mt][2] = p[4];
                a[mt][1] = p[68 * 8];  a[mt][3] = p[68 * 8 + 4];
            }
            #pragma unroll
            for (int nt = 0; nt < 8; ++nt) {
                uint32_t b0 = Vs[(ks * 8 + tg) * 72 + nt * 8 + grp];
                uint32_t b1 = Vs[(ks * 8 + tg + 4) * 72 + nt * 8 + grp];
                mma_tf32(o[0][nt], a[0], b0, b1);
                mma_tf32(o[1][nt], a[1], b0, b1);
            }
        }
    }

    // epilogue: normalize and store
    #pragma unroll
    for (int mt = 0; mt < 2; ++mt) {
        float inv0 = 1.0f / lrow[mt][0];
        float inv1 = 1.0f / lrow[mt][1];
        int row = qrow0 + row0 + mt * 16 + grp;
        #pragma unroll
        for (int nt = 0; nt < 8; ++nt) {
            int col = hoff + nt * 8 + tg * 2;
            *(float2*)&g_o[(size_t)row * Dm + col] =
                make_float2(o[mt][nt][0] * inv0, o[mt][nt][1] * inv0);
            *(float2*)&g_o[(size_t)(row + 8) * Dm + col] =
                make_float2(o[mt][nt][2] * inv1, o[mt][nt][3] * inv1);
        }
    }
}

// ---------------------------------------------------------------------------
extern "C" void kernel_launch(void* const* d_in, const int* in_sizes, int n_in,
                              void* d_out, int out_size)
{
    (void)in_sizes; (void)n_in; (void)out_size;
    const float* x    = (const float*)d_in[0];
    const float* Wq   = (const float*)d_in[1];
    const float* Wkv  = (const float*)d_in[2];
    const float* Wout = (const float*)d_in[3];
    float* out = (float*)d_out;

    float *q, *k, *v, *o;
    cudaGetSymbolAddress((void**)&q, g_q);
    cudaGetSymbolAddress((void**)&k, g_k);
    cudaGetSymbolAddress((void**)&v, g_v);
    cudaGetSymbolAddress((void**)&o, g_o);

    cudaFuncSetAttribute(attn_tf32,
                         cudaFuncAttributeMaxDynamicSharedMemorySize, 105472);

    dim3 blk(256);
    dim3 ggrid(Dm / 128, Rows / 128);   // (4, 32)

    // Projections (tf32 tensor cores). RMS-norm fused into Q/K epilogues:
    // Q also folds scale*log2e so softmax runs directly in exp2 domain.
    gemm_tf32<<<ggrid, blk>>>(x, Wq, q, Rows, Dm, Dm, SCALEv * LOG2E);
    gemm_tf32<<<ggrid, blk>>>(x, Wkv, k, Rows, Dm, Dm, 1.0f);
    gemm_tf32<<<ggrid, blk>>>(x, Wkv + (size_t)Dm * Dm, v, Rows, Dm, Dm, 0.0f);

    // Attention (2 CTAs/SM)
    attn_tf32<<<dim3(Sn / 128, Hh, Bb), 128, 105472>>>();

    // Output projection
    gemm_tf32<<<ggrid, blk>>>(o, Wout, out, Rows, Dm, Dm, 0.0f);
}